// round 6
// baseline (speedup 1.0000x reference)
#include <cuda_runtime.h>
#include <cuda_bf16.h>

// SSIM loss — band kernel, software-pipelined: next batch's global loads are
// issued before the horizontal smem phase, hiding DRAM latency. Double-
// buffered packed column-sum planes; one barrier per batch.

#define IMG    512
#define CROP   492
#define SHAVE  10
#define PLANE  (IMG * IMG)

#define NBANDS 16
#define RROWS  32
#define GROWS  4
#define NBATCH (RROWS / GROWS)    // 8
#define WID4   512
#define WIDS   576
#define NT     512
#define NBLOCKS (NBANDS * 16)     // 256

#define SWZ4(i) ((i) ^ (((i) >> 3) & 7))
#define SWZS(i) ((i) + ((i) >> 3))
#define Q4(b, g, i) ((((b) * GROWS + (g)) * WID4) + SWZ4(i))
#define Q1(b, g, i) ((((b) * GROWS + (g)) * WIDS) + SWZS(i))

#define CS4_ELEMS (2 * GROWS * WID4)
#define CS1_ELEMS (2 * GROWS * WIDS)
#define SMEM_BYTES (CS4_ELEMS * 16 + CS1_ELEMS * 4)   // 83968

__device__ double   g_part[NBLOCKS];
__device__ unsigned g_count = 0;

__device__ __forceinline__ float yval(float c0, float c1, float c2)
{
    const float w0 = 65.738f  / 256.0f;
    const float w1 = 129.057f / 256.0f;
    const float w2 = 25.064f  / 256.0f;
    const float inv255 = 1.0f / 255.0f;
    return w0 * __saturatef(c0 * inv255)
         + w1 * __saturatef(c1 * inv255)
         + w2 * __saturatef(c2 * inv255);
}

__device__ __forceinline__ void push(
    float a, float b, float (&wa)[11], float (&wb)[11],
    float& Sa, float& Sb, float& Saa, float& Sbb, float& Sab)
{
    float oa = wa[0], ob = wb[0];
    Sa  += a - oa;
    Sb  += b - ob;
    Saa += a * a - oa * oa;
    Sbb += b * b - ob * ob;
    Sab += a * b - oa * ob;
    #pragma unroll
    for (int k = 0; k < 10; k++) { wa[k] = wa[k + 1]; wb[k] = wb[k + 1]; }
    wa[10] = a; wb[10] = b;
}

__global__ __launch_bounds__(NT, 2)
void ssim_band_kernel(const float* __restrict__ sr, const float* __restrict__ hr,
                      float* __restrict__ out, const void* __restrict__ bs_ptr)
{
    extern __shared__ char smem_raw[];
    float4* cs4 = (float4*)smem_raw;
    float*  cs1 = (float*)(smem_raw + CS4_ELEMS * 16);

    __shared__ float  redf[NT / 32];
    __shared__ double redd[NT / 32];
    __shared__ int    s_last;

    const int t    = threadIdx.x;
    const int band = blockIdx.x;
    const int n    = blockIdx.y;
    const int oy0  = band * RROWS;

    const float* A = sr + (size_t)n * 3 * PLANE;
    const float* B = hr + (size_t)n * 3 * PLANE;

    // zero both buffers (halo cells stay zero forever)
    for (int i = t; i < CS4_ELEMS; i += NT) cs4[i] = make_float4(0.f, 0.f, 0.f, 0.f);
    for (int i = t; i < CS1_ELEMS; i += NT) cs1[i] = 0.0f;
    __syncthreads();

    float wa[11], wb[11];
    #pragma unroll
    for (int k = 0; k < 11; k++) { wa[k] = 0.0f; wb[k] = 0.0f; }
    float Sa = 0.f, Sb = 0.f, Saa = 0.f, Sbb = 0.f, Sab = 0.f;

    const bool col_ok = (t < CROP);
    int ry  = oy0 - 5;
    int off = (ry + SHAVE) * IMG + (t + SHAVE);

    // ---- warm-up: 10 row inserts ----
    #pragma unroll
    for (int i = 0; i < 10; i++) {
        bool v = col_ok && (ry >= 0) && (ry < CROP);
        float a = 0.f, b = 0.f;
        if (v) {
            a = yval(A[off], A[off + PLANE], A[off + 2*PLANE]);
            b = yval(B[off], B[off + PLANE], B[off + 2*PLANE]);
        }
        push(a, b, wa, wb, Sa, Sb, Saa, Sbb, Sab);
        ry++; off += IMG;
    }

    // ---- batch 0 vertical into buffer 0 ----
    #pragma unroll
    for (int g = 0; g < GROWS; g++) {
        int gy = oy0 + g;
        bool v = col_ok && (ry < CROP);
        float a = 0.f, b = 0.f;
        if (v) {
            a = yval(A[off], A[off + PLANE], A[off + 2*PLANE]);
            b = yval(B[off], B[off + PLANE], B[off + 2*PLANE]);
        }
        push(a, b, wa, wb, Sa, Sb, Saa, Sbb, Sab);
        ry++; off += IMG;
        if (col_ok && gy < CROP) {
            int ix = t + 5;
            cs4[Q4(0, g, ix)] = make_float4(Sa, Sb, Saa, Sbb);
            cs1[Q1(0, g, ix)] = Sab;
        }
    }
    __syncthreads();

    const float inv121 = 1.0f / 121.0f;
    const float C1 = 6.5025f;
    const float C2 = 58.5225f;

    float acc = 0.0f;

    #pragma unroll
    for (int jb = 0; jb < NBATCH; jb++) {
        const int cur = jb & 1, nxt = cur ^ 1;
        const bool have_next = (jb + 1 < NBATCH);

        // ---- issue next batch's global loads (latency hidden by horizontal) ----
        float ra0[GROWS], ra1[GROWS], ra2[GROWS];
        float rb0[GROWS], rb1[GROWS], rb2[GROWS];
        if (have_next) {
            #pragma unroll
            for (int g = 0; g < GROWS; g++) {
                bool v = col_ok && (ry + g < CROP);
                int o = off + g * IMG;
                ra0[g] = v ? A[o]             : 0.0f;
                ra1[g] = v ? A[o + PLANE]     : 0.0f;
                ra2[g] = v ? A[o + 2*PLANE]   : 0.0f;
                rb0[g] = v ? B[o]             : 0.0f;
                rb1[g] = v ? B[o + PLANE]     : 0.0f;
                rb2[g] = v ? B[o + 2*PLANE]   : 0.0f;
            }
        }

        // ---- horizontal on current buffer ----
        if (t < 492) {
            int row = t / 123;            // 0..3
            int run = t % 123;            // 0..122
            int x0  = run * 4;
            int gy  = oy0 + jb * GROWS + row;
            if (gy < CROP) {
                float H0 = 0.f, H1 = 0.f, H2 = 0.f, H3 = 0.f, H4 = 0.f;
                #pragma unroll
                for (int d = 0; d < 11; d++) {
                    float4 q = cs4[Q4(cur, row, x0 + d)];
                    H0 += q.x; H1 += q.y; H2 += q.z; H3 += q.w;
                    H4 += cs1[Q1(cur, row, x0 + d)];
                }
                #pragma unroll
                for (int m = 0; m < 4; m++) {
                    // x0+m <= 491 < CROP always: no bound check needed
                    float mu1 = H0 * inv121;
                    float mu2 = H1 * inv121;
                    float mu1_sq  = mu1 * mu1;
                    float mu2_sq  = mu2 * mu2;
                    float mu1_mu2 = mu1 * mu2;
                    float sig1  = H2 * inv121 - mu1_sq;
                    float sig2  = H3 * inv121 - mu2_sq;
                    float sig12 = H4 * inv121 - mu1_mu2;
                    float num = (2.0f * mu1_mu2 + C1) * (2.0f * sig12 + C2);
                    float den = (mu1_sq + mu2_sq + C1) * (sig1 + sig2 + C2);
                    acc += 1.0f - __fdividef(num, den);
                    if (m < 3) {
                        float4 qo = cs4[Q4(cur, row, x0 + m)];
                        float4 qn = cs4[Q4(cur, row, x0 + m + 11)];
                        H0 += qn.x - qo.x;
                        H1 += qn.y - qo.y;
                        H2 += qn.z - qo.z;
                        H3 += qn.w - qo.w;
                        H4 += cs1[Q1(cur, row, x0 + m + 11)] - cs1[Q1(cur, row, x0 + m)];
                    }
                }
            }
        }

        // ---- consume prefetched rows: window update + emit to other buffer ----
        if (have_next) {
            #pragma unroll
            for (int g = 0; g < GROWS; g++) {
                float a = yval(ra0[g], ra1[g], ra2[g]);
                float b = yval(rb0[g], rb1[g], rb2[g]);
                push(a, b, wa, wb, Sa, Sb, Saa, Sbb, Sab);
                int gy2 = oy0 + (jb + 1) * GROWS + g;
                if (col_ok && gy2 < CROP) {
                    int ix = t + 5;
                    cs4[Q4(nxt, g, ix)] = make_float4(Sa, Sb, Saa, Sbb);
                    cs1[Q1(nxt, g, ix)] = Sab;
                }
            }
            ry  += GROWS;
            off += GROWS * IMG;
        }
        __syncthreads();
    }

    // ---- block reduction -> per-block partial ----
    #pragma unroll
    for (int o = 16; o > 0; o >>= 1)
        acc += __shfl_down_sync(0xffffffffu, acc, o);
    int lane = t & 31, warp = t >> 5;
    if (lane == 0) redf[warp] = acc;
    __syncthreads();
    if (warp == 0) {
        float v = (lane < NT / 32) ? redf[lane] : 0.0f;
        #pragma unroll
        for (int o = 16; o > 0; o >>= 1)
            v += __shfl_down_sync(0xffffffffu, v, o);
        if (lane == 0)
            g_part[n * NBANDS + band] = (double)v;
    }

    // ---- last block performs the global reduction ----
    if (t == 0) {
        __threadfence();
        unsigned old = atomicAdd(&g_count, 1u);
        s_last = (old == NBLOCKS - 1) ? 1 : 0;
    }
    __syncthreads();
    if (s_last) {
        double v = (t < NBLOCKS) ? g_part[t] : 0.0;
        #pragma unroll
        for (int o = 16; o > 0; o >>= 1)
            v += __shfl_down_sync(0xffffffffu, v, o);
        if (lane == 0) redd[warp] = v;
        __syncthreads();
        if (warp == 0) {
            double s = (lane < NT / 32) ? redd[lane] : 0.0;
            #pragma unroll
            for (int o = 16; o > 0; o >>= 1)
                s += __shfl_down_sync(0xffffffffu, s, o);
            if (lane == 0) {
                float divisor = 16.0f;
                if (bs_ptr) {
                    int vi = *(const int*)bs_ptr;
                    if (vi > 0 && vi < 100000000) divisor = (float)vi;
                    else {
                        float vf = *(const float*)bs_ptr;
                        if (vf > 0.0f && vf < 1.0e8f) divisor = vf;
                    }
                }
                out[0]  = (float)(s / (double)divisor);
                g_count = 0;   // reset for next graph replay
            }
        }
    }
}

extern "C" void kernel_launch(void* const* d_in, const int* in_sizes, int n_in,
                              void* d_out, int out_size)
{
    const float* sr = (const float*)d_in[0];
    const float* hr = (const float*)d_in[1];
    const void* bs  = (n_in >= 3) ? d_in[2] : nullptr;
    float* out = (float*)d_out;

    cudaFuncSetAttribute(ssim_band_kernel,
                         cudaFuncAttributeMaxDynamicSharedMemorySize, SMEM_BYTES);

    dim3 grid(NBANDS, 16);
    ssim_band_kernel<<<grid, NT, SMEM_BYTES>>>(sr, hr, out, bs);
}

// round 7
// speedup vs baseline: 1.4682x; 1.4682x over previous
#include <cuda_runtime.h>
#include <cuda_bf16.h>

// SSIM loss — band kernel (R5 structure) with 4-quantity reformulation:
// box sums of p=a+b, m=a-b, p^2, m^2 suffice for SSIM:
//   mu1*mu2      = (muP^2 - muM^2)/4
//   mu1^2+mu2^2  = (muP^2 + muM^2)/2
//   box(ab)      = (PP - MM)/4
//   box(a^2+b^2) = (PP + MM)/2
// One float4 smem plane, one STS.128 per emit, one LDS.128 per tap.

#define IMG    512
#define CROP   492
#define SHAVE  10
#define PLANE  (IMG * IMG)

#define NBANDS 16
#define RROWS  32
#define GROWS  8
#define NBATCH (RROWS / GROWS)   // 4
#define WID4   512
#define NT     512
#define NBLOCKS (NBANDS * 16)    // 256

#define SWZ4(i) ((i) ^ (((i) >> 3) & 7))
#define Q4(g, i) ((g) * WID4 + SWZ4(i))

#define SMEM_BYTES (GROWS * WID4 * 16)   // 65536

__device__ double   g_part[NBLOCKS];
__device__ unsigned g_count = 0;

__device__ __forceinline__ float yval(float c0, float c1, float c2)
{
    const float w0 = 65.738f  / 256.0f;
    const float w1 = 129.057f / 256.0f;
    const float w2 = 25.064f  / 256.0f;
    const float inv255 = 1.0f / 255.0f;
    return w0 * __saturatef(c0 * inv255)
         + w1 * __saturatef(c1 * inv255)
         + w2 * __saturatef(c2 * inv255);
}

// push p=a+b, m=a-b into 11-deep sliding windows; maintain 4 running sums
__device__ __forceinline__ void push(
    float p, float m, float (&wp)[11], float (&wm)[11],
    float& Sp, float& Sm, float& Spp, float& Smm)
{
    float op = wp[0], om = wm[0];
    Sp  += p - op;
    Sm  += m - om;
    Spp += p * p - op * op;
    Smm += m * m - om * om;
    #pragma unroll
    for (int k = 0; k < 10; k++) { wp[k] = wp[k + 1]; wm[k] = wm[k + 1]; }
    wp[10] = p; wm[10] = m;
}

__global__ __launch_bounds__(NT, 2)
void ssim_band_kernel(const float* __restrict__ sr, const float* __restrict__ hr,
                      float* __restrict__ out, const void* __restrict__ bs_ptr)
{
    extern __shared__ char smem_raw[];
    float4* cs4 = (float4*)smem_raw;      // [GROWS][WID4] packed (Sp,Sm,Spp,Smm)

    __shared__ float  redf[NT / 32];
    __shared__ double redd[NT / 32];
    __shared__ int    s_last;

    const int t    = threadIdx.x;
    const int band = blockIdx.x;
    const int n    = blockIdx.y;
    const int oy0  = band * RROWS;

    const float* A = sr + (size_t)n * 3 * PLANE;
    const float* B = hr + (size_t)n * 3 * PLANE;

    // zero cs plane once: halo cells stay zero forever
    for (int i = t; i < GROWS * WID4; i += NT)
        cs4[i] = make_float4(0.f, 0.f, 0.f, 0.f);

    float wp[11], wm[11];
    #pragma unroll
    for (int k = 0; k < 11; k++) { wp[k] = 0.0f; wm[k] = 0.0f; }
    float Sp = 0.f, Sm = 0.f, Spp = 0.f, Smm = 0.f;

    const bool col_ok = (t < CROP);
    int ry  = oy0 - 5;
    int off = (ry + SHAVE) * IMG + (t + SHAVE);

    // ---- warm-up: 10 row inserts ----
    #pragma unroll
    for (int i = 0; i < 10; i++) {
        bool v = col_ok && (ry >= 0) && (ry < CROP);
        float p = 0.f, m = 0.f;
        if (v) {
            float a = yval(A[off], A[off + PLANE], A[off + 2*PLANE]);
            float b = yval(B[off], B[off + PLANE], B[off + 2*PLANE]);
            p = a + b; m = a - b;
        }
        push(p, m, wp, wm, Sp, Sm, Spp, Smm);
        ry++; off += IMG;
    }
    __syncthreads();

    const float inv121 = 1.0f / 121.0f;
    const float C1 = 6.5025f;
    const float C2 = 58.5225f;

    float acc = 0.0f;

    #pragma unroll
    for (int jb = 0; jb < NBATCH; jb++) {
        // ---- vertical: insert GROWS rows, emit one packed float4 ----
        #pragma unroll
        for (int g = 0; g < GROWS; g++) {
            int gy = oy0 + jb * GROWS + g;
            bool v = col_ok && (ry < CROP);
            float p = 0.f, m = 0.f;
            if (v) {
                float a = yval(A[off], A[off + PLANE], A[off + 2*PLANE]);
                float b = yval(B[off], B[off + PLANE], B[off + 2*PLANE]);
                p = a + b; m = a - b;
            }
            push(p, m, wp, wm, Sp, Sm, Spp, Smm);
            ry++; off += IMG;
            if (col_ok && gy < CROP)
                cs4[Q4(g, t + 5)] = make_float4(Sp, Sm, Spp, Smm);
        }
        __syncthreads();

        // ---- horizontal: runs of 8 outputs, sliding windows ----
        if (t < 496) {
            int row = t / 62;             // 0..7
            int run = t % 62;             // 0..61
            int x0  = run * 8;
            int gy  = oy0 + jb * GROWS + row;
            if (gy < CROP) {
                float HP = 0.f, HM = 0.f, HPP = 0.f, HMM = 0.f;
                #pragma unroll
                for (int d = 0; d < 11; d++) {
                    float4 q = cs4[Q4(row, x0 + d)];
                    HP += q.x; HM += q.y; HPP += q.z; HMM += q.w;
                }
                #pragma unroll
                for (int mm = 0; mm < 8; mm++) {
                    if (x0 + mm < CROP) {
                        float muP = HP * inv121;
                        float muM = HM * inv121;
                        float muP2 = muP * muP;
                        float muM2 = muM * muM;
                        float mu1mu2 = 0.25f * (muP2 - muM2);
                        float musq   = 0.5f  * (muP2 + muM2);
                        float sab    = 0.25f * (HPP - HMM);   // box(ab)
                        float ssq    = 0.5f  * (HPP + HMM);   // box(a^2+b^2)
                        float sigma12 = fmaf(sab, inv121, -mu1mu2);
                        float sigsum  = fmaf(ssq, inv121, -musq);
                        float num = fmaf(2.0f, mu1mu2, C1) * fmaf(2.0f, sigma12, C2);
                        float den = (musq + C1) * (sigsum + C2);
                        acc += 1.0f - __fdividef(num, den);
                    }
                    if (mm < 7) {
                        float4 qo = cs4[Q4(row, x0 + mm)];
                        float4 qn = cs4[Q4(row, x0 + mm + 11)];
                        HP  += qn.x - qo.x;
                        HM  += qn.y - qo.y;
                        HPP += qn.z - qo.z;
                        HMM += qn.w - qo.w;
                    }
                }
            }
        }
        __syncthreads();
    }

    // ---- block reduction -> per-block partial ----
    #pragma unroll
    for (int o = 16; o > 0; o >>= 1)
        acc += __shfl_down_sync(0xffffffffu, acc, o);
    int lane = t & 31, warp = t >> 5;
    if (lane == 0) redf[warp] = acc;
    __syncthreads();
    if (warp == 0) {
        float v = (lane < NT / 32) ? redf[lane] : 0.0f;
        #pragma unroll
        for (int o = 16; o > 0; o >>= 1)
            v += __shfl_down_sync(0xffffffffu, v, o);
        if (lane == 0)
            g_part[n * NBANDS + band] = (double)v;
    }

    // ---- last block performs the global reduction ----
    if (t == 0) {
        __threadfence();
        unsigned old = atomicAdd(&g_count, 1u);
        s_last = (old == NBLOCKS - 1) ? 1 : 0;
    }
    __syncthreads();
    if (s_last) {
        double v = (t < NBLOCKS) ? g_part[t] : 0.0;
        #pragma unroll
        for (int o = 16; o > 0; o >>= 1)
            v += __shfl_down_sync(0xffffffffu, v, o);
        if (lane == 0) redd[warp] = v;
        __syncthreads();
        if (warp == 0) {
            double s = (lane < NT / 32) ? redd[lane] : 0.0;
            #pragma unroll
            for (int o = 16; o > 0; o >>= 1)
                s += __shfl_down_sync(0xffffffffu, s, o);
            if (lane == 0) {
                float divisor = 16.0f;
                if (bs_ptr) {
                    int vi = *(const int*)bs_ptr;
                    if (vi > 0 && vi < 100000000) divisor = (float)vi;
                    else {
                        float vf = *(const float*)bs_ptr;
                        if (vf > 0.0f && vf < 1.0e8f) divisor = vf;
                    }
                }
                out[0]  = (float)(s / (double)divisor);
                g_count = 0;   // reset for next graph replay
            }
        }
    }
}

extern "C" void kernel_launch(void* const* d_in, const int* in_sizes, int n_in,
                              void* d_out, int out_size)
{
    const float* sr = (const float*)d_in[0];
    const float* hr = (const float*)d_in[1];
    const void* bs  = (n_in >= 3) ? d_in[2] : nullptr;
    float* out = (float*)d_out;

    cudaFuncSetAttribute(ssim_band_kernel,
                         cudaFuncAttributeMaxDynamicSharedMemorySize, SMEM_BYTES);

    dim3 grid(NBANDS, 16);
    ssim_band_kernel<<<grid, NT, SMEM_BYTES>>>(sr, hr, out, bs);
}